// round 16
// baseline (speedup 1.0000x reference)
#include <cuda_runtime.h>
#include <cuda_bf16.h>
#include <cstdint>

// ---------------- problem dims ----------------
#define B_    32
#define CIN   256
#define H_    56
#define W_    56
#define COUT  256
#define HP    58
#define WP    58
#define HW    (H_*W_)            // 3136
#define M_TOTAL (B_*HW)          // 100352
#define TILE_M 64
#define N_TILES (M_TOTAL/TILE_M) // 1568 work items
#define GRID   304               // persistent CTAs, 2 per SM
#define NSTAGE  36               // 9 taps * (256/64 int8 k-chunks)
#define THREADS 256
#define QLOW  (-128.0f)
#define QUP   (127.0f)

// ---------------- scratch (device globals; no allocs) ----------------
__device__ __align__(16) char g_xq[(size_t)B_*HP*WP*CIN];   // padded NHWC int8 x
__device__ __align__(16) char g_wq[NSTAGE*COUT*64];          // [stage][n][64] int8 weights
__device__ int g_tile_ctr;                                   // work-stealing counter

// ---------------- PTX helpers ----------------
__device__ __forceinline__ uint32_t smem_to_u32(const void* p) {
    uint32_t a;
    asm("{ .reg .u64 t; cvta.to.shared.u64 t, %1; cvt.u32.u64 %0, t; }" : "=r"(a) : "l"(p));
    return a;
}
__device__ __forceinline__ void cp_async16(uint32_t dst, const void* src) {
    asm volatile("cp.async.cg.shared.global [%0], [%1], 16;" :: "r"(dst), "l"(src));
}
#define CP_COMMIT() asm volatile("cp.async.commit_group;" ::: "memory")
#define CP_WAIT(n)  asm volatile("cp.async.wait_group %0;" :: "n"(n) : "memory")

__device__ __forceinline__ void ldsm_x4(uint32_t& r0, uint32_t& r1, uint32_t& r2, uint32_t& r3,
                                        uint32_t addr) {
    asm volatile("ldmatrix.sync.aligned.m8n8.x4.shared.b16 {%0,%1,%2,%3}, [%4];"
                 : "=r"(r0), "=r"(r1), "=r"(r2), "=r"(r3) : "r"(addr));
}
__device__ __forceinline__ void mma_s8(int* d, const uint32_t* a, const uint32_t* b) {
    asm volatile("mma.sync.aligned.m16n8k32.row.col.s32.s8.s8.s32 "
                 "{%0,%1,%2,%3},{%4,%5,%6,%7},{%8,%9},{%0,%1,%2,%3};"
                 : "+r"(d[0]), "+r"(d[1]), "+r"(d[2]), "+r"(d[3])
                 : "r"(a[0]), "r"(a[1]), "r"(a[2]), "r"(a[3]), "r"(b[0]), "r"(b[1]));
}

// ---------------- merged prep kernel ----------------
// Blocks 0..255: weight quant (+ work counter reset). Blocks 256..2047: x quant.
#define WQ_BLOCKS 256
__global__ void prep_kernel(const float* __restrict__ x, const float* __restrict__ w,
                            const float* __restrict__ sw, const float* __restrict__ sx) {
    __shared__ char tile[56 * 260];                    // used by xquant blocks only
    int tid = threadIdx.x;

    if (blockIdx.x == 0 && tid == 0) g_tile_ctr = 0;   // reset work queue each launch

    if (blockIdx.x < WQ_BLOCKS) {
        // ---- weight quant: thread = (n, cin), coalesced both sides ----
        int idx = blockIdx.x * THREADS + tid;          // < 65536
        int n   = idx >> 8;
        int cin = idx & 255;
        float s = sw[n];
        const float* wp = w + (size_t)n * 2304 + (size_t)cin * 9;
        char* dst = g_wq + (size_t)(cin >> 6) * 16384 + (size_t)n * 64 + (cin & 63);
#pragma unroll
        for (int kk = 0; kk < 9; ++kk) {
            float q = rintf(fminf(fmaxf(wp[kk] * s, QLOW), QUP));
            dst[(size_t)kk * 4 * 16384] = (char)(int)q;
        }
        return;
    }

    // ---- x quant: one block per (b, y) row ----
    int bid = blockIdx.x - WQ_BLOCKS;
    int b = bid / H_;
    int y = bid - b * H_;

    // border zeroing: cells p = y + 56*pi (pi = tid>>4 in 0..15, used while p<228)
    {
        int pi = tid >> 4, cv = tid & 15;
        int p = y + pi * 56;
        if (p < 228) {
            int yp, xp;
            if (p < 58)       { yp = 0;  xp = p; }
            else if (p < 116) { yp = 57; xp = p - 58; }
            else { int q = p - 116; yp = 1 + (q >> 1); xp = (q & 1) ? 57 : 0; }
            *(uint4*)(g_xq + ((size_t)(b * HP + yp) * WP + xp) * CIN + (size_t)cv * 16) =
                make_uint4(0, 0, 0, 0);
        }
    }

    float s = sx[0];
#pragma unroll
    for (int it = 0; it < 14; ++it) {
        int idx = it * 256 + tid;                      // < 3584
        int c  = idx / 14;
        int x4 = idx - c * 14;
        float4 v = *(const float4*)(x + ((size_t)(b * CIN + c) * H_ + y) * W_ + x4 * 4);
        int xx = x4 * 4;
        tile[(xx + 0) * 260 + c] = (char)(int)rintf(fminf(fmaxf(v.x * s, QLOW), QUP));
        tile[(xx + 1) * 260 + c] = (char)(int)rintf(fminf(fmaxf(v.y * s, QLOW), QUP));
        tile[(xx + 2) * 260 + c] = (char)(int)rintf(fminf(fmaxf(v.z * s, QLOW), QUP));
        tile[(xx + 3) * 260 + c] = (char)(int)rintf(fminf(fmaxf(v.w * s, QLOW), QUP));
    }
    __syncthreads();
    char* dst = g_xq + ((size_t)(b * HP + (y + 1)) * WP + 1) * CIN;
#pragma unroll 1
    for (int it = 0; it < 14; ++it) {                  // 3584 u32 writes
        int idx = it * 256 + tid;
        int xx = idx >> 6;
        int c4 = idx & 63;
        uint32_t v = *(const uint32_t*)&tile[xx * 260 + c4 * 4];
        *(uint32_t*)(dst + (size_t)xx * CIN + c4 * 4) = v;
    }
}

// ---------------- main conv kernel: persistent int8 mma.sync implicit GEMM ----
// 304 persistent CTAs (2/SM), dynamic tile stealing via g_tile_ctr.
// Per tile: 64x256, warp tile 32x64, 4-stage cp.async ring (R13-proven inner loop).
#define SM_SCALE 0
#define SM_BIAS  1024
#define SM_A     2048
#define SM_B     (2048 + 4*4096)          // 18432
#define SMEM_BYTES (SM_B + 4*16384)       // 83968

__global__ __launch_bounds__(THREADS, 2) void conv_mma_kernel(
    const float* __restrict__ bias, const float* __restrict__ sw,
    const float* __restrict__ sx, float* __restrict__ out)
{
    extern __shared__ char smem[];
    __shared__ int s_tile;
    uint32_t sb = smem_to_u32(smem);
    int tid  = threadIdx.x;
    int wid  = tid >> 5, lane = tid & 31;
    int warp_m = (wid & 1) * 32;          // 2 warps over M=64
    int warp_n = (wid >> 1) * 64;         // 4 warps over N=256

    {                                     // scale + bias to smem (once per CTA)
        float s = sx[0];
        ((float*)(smem + SM_SCALE))[tid] = 1.0f / (s * sw[tid]);
        ((float*)(smem + SM_BIAS))[tid]  = bias[tid];
    }

    // ---- tile-invariant geometry ----
    // A smem dst: thread t -> row t>>2, seg c = t&3
    uint32_t aDst0;
    {
        int row = tid >> 2, c = tid & 3;
        aDst0 = sb + SM_A + (uint32_t)row * 64 + (uint32_t)((c ^ ((row >> 1) & 3)) << 4);
    }
    // B: 256 rows x 64B; thread t -> row t, segs c = 0..3
    const char* bSrc0 = g_wq + (size_t)tid * 64;
    uint32_t bDst[4];
    {
        int sw2 = (tid >> 1) & 3;
        uint32_t base = sb + SM_B + (uint32_t)tid * 64;
#pragma unroll
        for (int c = 0; c < 4; ++c) bDst[c] = base + (uint32_t)((c ^ sw2) << 4);
    }
    // per-lane ldmatrix geometry
    int aR   = (lane & 7) + ((lane >> 3) & 1) * 8;      // A row within m16 frag
    int aCH  = lane >> 4;                               // A k-half selector
    uint32_t aRowByte = (uint32_t)(warp_m + aR) * 64;
    int aSw  = (aR >> 1) & 3;
    int bR   = (lane & 7) + ((lane >> 4) << 3);         // B row within n16 group
    int bCH  = (lane >> 3) & 1;
    uint32_t bRowByte = (uint32_t)(warp_n + bR) * 64;
    int bSw  = (bR >> 1) & 3;

#pragma unroll 1
    while (true) {
        if (tid == 0) s_tile = atomicAdd(&g_tile_ctr, 1);
        __syncthreads();                  // broadcast tile id; also fences ring reuse
        int tile = s_tile;
        if (tile >= N_TILES) break;
        int m0 = tile * TILE_M;

        // per-tile A gmem base (row = tid>>2 of the M-tile)
        const char* aSrc0;
        {
            int m = m0 + (tid >> 2);
            int b = m / HW; int rem = m - b * HW;
            int y = rem / W_; int x = rem - y * W_;
            aSrc0 = g_xq + ((size_t)((b * HP + y) * WP + x)) * CIN + (tid & 3) * 16;
        }

        int acc[2][8][4];
#pragma unroll
        for (int f = 0; f < 2; ++f)
#pragma unroll
            for (int g = 0; g < 8; ++g)
#pragma unroll
                for (int r = 0; r < 4; ++r) acc[f][g][r] = 0;

        // ---- prologue: stages 0..2 in flight ----
#pragma unroll
        for (int s = 0; s < 3; ++s) {
            int kk = s >> 2, kc = s & 3;
            int dy = kk / 3, dx = kk - dy * 3;
            cp_async16(aDst0 + (uint32_t)s * 4096, aSrc0 + (dy * WP + dx) * CIN + kc * 64);
            const char* bs2 = bSrc0 + (size_t)s * 16384;
#pragma unroll
            for (int c = 0; c < 4; ++c)
                cp_async16(bDst[c] + (uint32_t)s * 16384, bs2 + c * 16);
            CP_COMMIT();
        }

#pragma unroll 1
        for (int s = 0; s < NSTAGE; ++s) {
            CP_WAIT(2);                    // stage s resident (FIFO group completion)
            __syncthreads();               // writes visible; prior reads of slot (s+3)&3 done

            if (s + 3 < NSTAGE) {          // issue stage s+3 into ring slot (s+3)&3
                int sg = s + 3;
                int slot = sg & 3;
                int kk = sg >> 2, kc = sg & 3;
                int dy = kk / 3, dx = kk - dy * 3;
                cp_async16(aDst0 + (uint32_t)slot * 4096,
                           aSrc0 + (dy * WP + dx) * CIN + kc * 64);
                const char* bs2 = bSrc0 + (size_t)sg * 16384;
#pragma unroll
                for (int c = 0; c < 4; ++c)
                    cp_async16(bDst[c] + (uint32_t)slot * 16384, bs2 + c * 16);
            }
            CP_COMMIT();                   // always commit (possibly empty): uniform group math

            int bufc = s & 3;
            uint32_t smA = sb + SM_A + (uint32_t)bufc * 4096;
            uint32_t smB = sb + SM_B + (uint32_t)bufc * 16384;
#pragma unroll
            for (int s2 = 0; s2 < 2; ++s2) {
                uint32_t a[2][4];
#pragma unroll
                for (int f = 0; f < 2; ++f)
                    ldsm_x4(a[f][0], a[f][1], a[f][2], a[f][3],
                            smA + aRowByte + (uint32_t)f * 1024 +
                            (uint32_t)(((s2 * 2 + aCH) ^ aSw) << 4));
                uint32_t b[8][2];
#pragma unroll
                for (int g = 0; g < 4; ++g)
                    ldsm_x4(b[2 * g][0], b[2 * g][1], b[2 * g + 1][0], b[2 * g + 1][1],
                            smB + bRowByte + (uint32_t)g * 1024 +
                            (uint32_t)(((s2 * 2 + bCH) ^ bSw) << 4));
#pragma unroll
                for (int f = 0; f < 2; ++f)
#pragma unroll
                    for (int g = 0; g < 8; ++g)
                        mma_s8(acc[f][g], a[f], b[g]);
            }
        }

        // ---- epilogue: acc * (1/(sx*sw[n])) + bias[n], scattered NCHW stores ----
        const float* scl = (const float*)(smem + SM_SCALE);
        const float* bs  = (const float*)(smem + SM_BIAS);
#pragma unroll
        for (int f = 0; f < 2; ++f) {
            int m1 = m0 + warp_m + f * 16 + (lane >> 2);
            int m2 = m1 + 8;
            int b1 = m1 / HW; int r1 = m1 - b1 * HW; int y1 = r1 / W_; int x1 = r1 - y1 * W_;
            int b2 = m2 / HW; int r2 = m2 - b2 * HW; int y2 = r2 / W_; int x2 = r2 - y2 * W_;
            float* p1 = out + (size_t)b1 * COUT * HW + (size_t)y1 * W_ + x1;
            float* p2 = out + (size_t)b2 * COUT * HW + (size_t)y2 * W_ + x2;
#pragma unroll
            for (int g = 0; g < 8; ++g) {
                int n = warp_n + g * 8 + (lane & 3) * 2;
                float s0 = scl[n], s1 = scl[n + 1];
                float z0 = bs[n],  z1 = bs[n + 1];
                p1[(size_t)n * HW]       = fmaf((float)acc[f][g][0], s0, z0);
                p1[(size_t)(n + 1) * HW] = fmaf((float)acc[f][g][1], s1, z1);
                p2[(size_t)n * HW]       = fmaf((float)acc[f][g][2], s0, z0);
                p2[(size_t)(n + 1) * HW] = fmaf((float)acc[f][g][3], s1, z1);
            }
        }
    }
}

// ---------------- launch ----------------
extern "C" void kernel_launch(void* const* d_in, const int* in_sizes, int n_in,
                              void* d_out, int out_size) {
    const float* x    = (const float*)d_in[0];
    const float* w    = (const float*)d_in[1];
    const float* bias = (const float*)d_in[2];
    const float* sw   = (const float*)d_in[3];
    const float* sx   = (const float*)d_in[4];
    float* out        = (float*)d_out;

    cudaFuncSetAttribute(conv_mma_kernel, cudaFuncAttributeMaxDynamicSharedMemorySize, SMEM_BYTES);

    prep_kernel<<<WQ_BLOCKS + B_ * H_, THREADS>>>(x, w, sw, sx);
    conv_mma_kernel<<<GRID, THREADS, SMEM_BYTES>>>(bias, sw, sx, out);
}

// round 17
// speedup vs baseline: 1.0122x; 1.0122x over previous
#include <cuda_runtime.h>
#include <cuda_bf16.h>
#include <cstdint>

// ---------------- problem dims ----------------
#define B_    32
#define CIN   256
#define H_    56
#define W_    56
#define COUT  256
#define HP    58
#define WP    58
#define HW    (H_*W_)            // 3136
#define M_TOTAL (B_*HW)          // 100352
#define TILE_M 64
#define N_TILES (M_TOTAL/TILE_M) // 1568 work items
#define GRID   304               // persistent CTAs, 2 per SM
#define NSTAGE  36               // 9 taps * (256/64 int8 k-chunks)
#define THREADS 256
#define QLOW  (-128.0f)
#define QUP   (127.0f)

// ---------------- scratch (device globals; no allocs) ----------------
__device__ __align__(16) char g_xq[(size_t)B_*HP*WP*CIN];   // padded NHWC int8 x
__device__ __align__(16) char g_wq[NSTAGE*COUT*64];          // [stage][n][64] int8 weights
__device__ int g_tile_ctr;                                   // work-stealing counter

// ---------------- PTX helpers ----------------
__device__ __forceinline__ uint32_t smem_to_u32(const void* p) {
    uint32_t a;
    asm("{ .reg .u64 t; cvta.to.shared.u64 t, %1; cvt.u32.u64 %0, t; }" : "=r"(a) : "l"(p));
    return a;
}
__device__ __forceinline__ void cp_async16(uint32_t dst, const void* src) {
    asm volatile("cp.async.cg.shared.global [%0], [%1], 16;" :: "r"(dst), "l"(src));
}
#define CP_COMMIT() asm volatile("cp.async.commit_group;" ::: "memory")
#define CP_WAIT(n)  asm volatile("cp.async.wait_group %0;" :: "n"(n) : "memory")

__device__ __forceinline__ void ldsm_x4(uint32_t& r0, uint32_t& r1, uint32_t& r2, uint32_t& r3,
                                        uint32_t addr) {
    asm volatile("ldmatrix.sync.aligned.m8n8.x4.shared.b16 {%0,%1,%2,%3}, [%4];"
                 : "=r"(r0), "=r"(r1), "=r"(r2), "=r"(r3) : "r"(addr));
}
__device__ __forceinline__ void mma_s8(int* d, const uint32_t* a, const uint32_t* b) {
    asm volatile("mma.sync.aligned.m16n8k32.row.col.s32.s8.s8.s32 "
                 "{%0,%1,%2,%3},{%4,%5,%6,%7},{%8,%9},{%0,%1,%2,%3};"
                 : "+r"(d[0]), "+r"(d[1]), "+r"(d[2]), "+r"(d[3])
                 : "r"(a[0]), "r"(a[1]), "r"(a[2]), "r"(a[3]), "r"(b[0]), "r"(b[1]));
}

// ---------------- merged prep kernel ----------------
// Blocks 0..255: weight quant (+ work counter reset). Blocks 256..2047: x quant.
#define WQ_BLOCKS 256
__global__ void prep_kernel(const float* __restrict__ x, const float* __restrict__ w,
                            const float* __restrict__ sw, const float* __restrict__ sx) {
    __shared__ char tile[56 * 260];                    // used by xquant blocks only
    int tid = threadIdx.x;

    if (blockIdx.x == 0 && tid == 0) g_tile_ctr = 0;   // reset work queue each launch

    if (blockIdx.x < WQ_BLOCKS) {
        // ---- weight quant: thread = (n, cin), coalesced both sides ----
        int idx = blockIdx.x * THREADS + tid;          // < 65536
        int n   = idx >> 8;
        int cin = idx & 255;
        float s = sw[n];
        const float* wp = w + (size_t)n * 2304 + (size_t)cin * 9;
        char* dst = g_wq + (size_t)(cin >> 6) * 16384 + (size_t)n * 64 + (cin & 63);
#pragma unroll
        for (int kk = 0; kk < 9; ++kk) {
            float q = rintf(fminf(fmaxf(wp[kk] * s, QLOW), QUP));
            dst[(size_t)kk * 4 * 16384] = (char)(int)q;
        }
        return;
    }

    // ---- x quant: one block per (b, y) row ----
    int bid = blockIdx.x - WQ_BLOCKS;
    int b = bid / H_;
    int y = bid - b * H_;

    // border zeroing: cells p = y + 56*pi (pi = tid>>4 in 0..15, used while p<228)
    {
        int pi = tid >> 4, cv = tid & 15;
        int p = y + pi * 56;
        if (p < 228) {
            int yp, xp;
            if (p < 58)       { yp = 0;  xp = p; }
            else if (p < 116) { yp = 57; xp = p - 58; }
            else { int q = p - 116; yp = 1 + (q >> 1); xp = (q & 1) ? 57 : 0; }
            *(uint4*)(g_xq + ((size_t)(b * HP + yp) * WP + xp) * CIN + (size_t)cv * 16) =
                make_uint4(0, 0, 0, 0);
        }
    }

    float s = sx[0];
#pragma unroll
    for (int it = 0; it < 14; ++it) {
        int idx = it * 256 + tid;                      // < 3584
        int c  = idx / 14;
        int x4 = idx - c * 14;
        float4 v = *(const float4*)(x + ((size_t)(b * CIN + c) * H_ + y) * W_ + x4 * 4);
        int xx = x4 * 4;
        tile[(xx + 0) * 260 + c] = (char)(int)rintf(fminf(fmaxf(v.x * s, QLOW), QUP));
        tile[(xx + 1) * 260 + c] = (char)(int)rintf(fminf(fmaxf(v.y * s, QLOW), QUP));
        tile[(xx + 2) * 260 + c] = (char)(int)rintf(fminf(fmaxf(v.z * s, QLOW), QUP));
        tile[(xx + 3) * 260 + c] = (char)(int)rintf(fminf(fmaxf(v.w * s, QLOW), QUP));
    }
    __syncthreads();
    char* dst = g_xq + ((size_t)(b * HP + (y + 1)) * WP + 1) * CIN;
#pragma unroll 1
    for (int it = 0; it < 14; ++it) {                  // 3584 u32 writes
        int idx = it * 256 + tid;
        int xx = idx >> 6;
        int c4 = idx & 63;
        uint32_t v = *(const uint32_t*)&tile[xx * 260 + c4 * 4];
        *(uint32_t*)(dst + (size_t)xx * CIN + c4 * 4) = v;
    }
}

// ---------------- main conv kernel: persistent, continuous pipeline ----------
// 304 persistent CTAs (2/SM), dynamic tile stealing. The cp.async ring never
// drains: stages 33..35 of tile t prefetch stages 0..2 of tile t+1 (same slot
// safety + commit accounting as the intra-tile case); the epilogue overlaps
// with the next tile's loads.
#define SM_SCALE 0
#define SM_BIAS  1024
#define SM_A     2048
#define SM_B     (2048 + 4*4096)          // 18432
#define SMEM_BYTES (SM_B + 4*16384)       // 83968

__global__ __launch_bounds__(THREADS, 2) void conv_mma_kernel(
    const float* __restrict__ bias, const float* __restrict__ sw,
    const float* __restrict__ sx, float* __restrict__ out)
{
    extern __shared__ char smem[];
    __shared__ int s_tile;
    uint32_t sb = smem_to_u32(smem);
    int tid  = threadIdx.x;
    int wid  = tid >> 5, lane = tid & 31;
    int warp_m = (wid & 1) * 32;          // 2 warps over M=64
    int warp_n = (wid >> 1) * 64;         // 4 warps over N=256

    {                                     // scale + bias to smem (once per CTA)
        float s = sx[0];
        ((float*)(smem + SM_SCALE))[tid] = 1.0f / (s * sw[tid]);
        ((float*)(smem + SM_BIAS))[tid]  = bias[tid];
    }

    // ---- tile-invariant geometry ----
    uint32_t aDst0;
    {
        int row = tid >> 2, c = tid & 3;
        aDst0 = sb + SM_A + (uint32_t)row * 64 + (uint32_t)((c ^ ((row >> 1) & 3)) << 4);
    }
    const char* bSrc0 = g_wq + (size_t)tid * 64;
    uint32_t bDst[4];
    {
        int sw2 = (tid >> 1) & 3;
        uint32_t base = sb + SM_B + (uint32_t)tid * 64;
#pragma unroll
        for (int c = 0; c < 4; ++c) bDst[c] = base + (uint32_t)((c ^ sw2) << 4);
    }
    int aR   = (lane & 7) + ((lane >> 3) & 1) * 8;
    int aCH  = lane >> 4;
    uint32_t aRowByte = (uint32_t)(warp_m + aR) * 64;
    int aSw  = (aR >> 1) & 3;
    int bR   = (lane & 7) + ((lane >> 4) << 3);
    int bCH  = (lane >> 3) & 1;
    uint32_t bRowByte = (uint32_t)(warp_n + bR) * 64;
    int bSw  = (bR >> 1) & 3;

    // ---- first tile fetch + prologue ----
    if (tid == 0) s_tile = atomicAdd(&g_tile_ctr, 1);
    __syncthreads();
    int tile = s_tile;
    const char* aSrc0 = g_xq;
    if (tile < N_TILES) {
        int m = tile * TILE_M + (tid >> 2);
        int b = m / HW; int rem = m - b * HW;
        int y = rem / W_; int x = rem - y * W_;
        aSrc0 = g_xq + ((size_t)((b * HP + y) * WP + x)) * CIN + (tid & 3) * 16;
#pragma unroll
        for (int s = 0; s < 3; ++s) {
            // stages 0..2: kk=0 (dy=dx=0), kc=s
            cp_async16(aDst0 + (uint32_t)s * 4096, aSrc0 + s * 64);
            const char* bs2 = bSrc0 + (size_t)s * 16384;
#pragma unroll
            for (int c = 0; c < 4; ++c)
                cp_async16(bDst[c] + (uint32_t)s * 16384, bs2 + c * 16);
            CP_COMMIT();
        }
    }

#pragma unroll 1
    while (tile < N_TILES) {
        int tile_next = N_TILES;
        const char* aSrc0_next = aSrc0;

        int acc[2][8][4];
#pragma unroll
        for (int f = 0; f < 2; ++f)
#pragma unroll
            for (int g = 0; g < 8; ++g)
#pragma unroll
                for (int r = 0; r < 4; ++r) acc[f][g][r] = 0;

#pragma unroll 1
        for (int s = 0; s < NSTAGE; ++s) {
            CP_WAIT(2);                    // stage s resident (FIFO group completion)
            __syncthreads();               // publishes writes; fences prior slot reads

            if (s == 32 && tid == 0) s_tile = atomicAdd(&g_tile_ctr, 1);

            int sg = s + 3;
            if (sg < NSTAGE) {             // current tile, stage sg -> slot sg&3
                int slot = sg & 3;
                int kk = sg >> 2, kc = sg & 3;
                int dy = kk / 3, dx = kk - dy * 3;
                cp_async16(aDst0 + (uint32_t)slot * 4096,
                           aSrc0 + (dy * WP + dx) * CIN + kc * 64);
                const char* bs2 = bSrc0 + (size_t)sg * 16384;
#pragma unroll
                for (int c = 0; c < 4; ++c)
                    cp_async16(bDst[c] + (uint32_t)slot * 16384, bs2 + c * 16);
            } else {                       // s >= 33: next tile's stage sg-36
                if (s == 33) {             // s_tile written at s==32, fenced by s==33 barrier
                    tile_next = s_tile;
                    if (tile_next < N_TILES) {
                        int m = tile_next * TILE_M + (tid >> 2);
                        int b = m / HW; int rem = m - b * HW;
                        int y = rem / W_; int x = rem - y * W_;
                        aSrc0_next = g_xq + ((size_t)((b * HP + y) * WP + x)) * CIN
                                   + (tid & 3) * 16;
                    }
                }
                if (tile_next < N_TILES) {
                    int sg2 = sg - NSTAGE; // 0,1,2 ; kk=0 (dy=dx=0), kc=sg2
                    int slot = sg & 3;     // == sg2 ; prior reads fenced by this stage's barrier
                    cp_async16(aDst0 + (uint32_t)slot * 4096, aSrc0_next + sg2 * 64);
                    const char* bs2 = bSrc0 + (size_t)sg2 * 16384;
#pragma unroll
                    for (int c = 0; c < 4; ++c)
                        cp_async16(bDst[c] + (uint32_t)slot * 16384, bs2 + c * 16);
                }
            }
            CP_COMMIT();                   // exactly one group per stage: uniform accounting

            int bufc = s & 3;
            uint32_t smA = sb + SM_A + (uint32_t)bufc * 4096;
            uint32_t smB = sb + SM_B + (uint32_t)bufc * 16384;
#pragma unroll
            for (int s2 = 0; s2 < 2; ++s2) {
                uint32_t a[2][4];
#pragma unroll
                for (int f = 0; f < 2; ++f)
                    ldsm_x4(a[f][0], a[f][1], a[f][2], a[f][3],
                            smA + aRowByte + (uint32_t)f * 1024 +
                            (uint32_t)(((s2 * 2 + aCH) ^ aSw) << 4));
                uint32_t b[8][2];
#pragma unroll
                for (int g = 0; g < 4; ++g)
                    ldsm_x4(b[2 * g][0], b[2 * g][1], b[2 * g + 1][0], b[2 * g + 1][1],
                            smB + bRowByte + (uint32_t)g * 1024 +
                            (uint32_t)(((s2 * 2 + bCH) ^ bSw) << 4));
#pragma unroll
                for (int f = 0; f < 2; ++f)
#pragma unroll
                    for (int g = 0; g < 8; ++g)
                        mma_s8(acc[f][g], a[f], b[g]);
            }
        }

        // ---- epilogue (overlaps with next tile's in-flight loads) ----
        int m0 = tile * TILE_M;
        const float* scl = (const float*)(smem + SM_SCALE);
        const float* bs  = (const float*)(smem + SM_BIAS);
#pragma unroll
        for (int f = 0; f < 2; ++f) {
            int m1 = m0 + warp_m + f * 16 + (lane >> 2);
            int m2 = m1 + 8;
            int b1 = m1 / HW; int r1 = m1 - b1 * HW; int y1 = r1 / W_; int x1 = r1 - y1 * W_;
            int b2 = m2 / HW; int r2 = m2 - b2 * HW; int y2 = r2 / W_; int x2 = r2 - y2 * W_;
            float* p1 = out + (size_t)b1 * COUT * HW + (size_t)y1 * W_ + x1;
            float* p2 = out + (size_t)b2 * COUT * HW + (size_t)y2 * W_ + x2;
#pragma unroll
            for (int g = 0; g < 8; ++g) {
                int n = warp_n + g * 8 + (lane & 3) * 2;
                float s0 = scl[n], s1 = scl[n + 1];
                float z0 = bs[n],  z1 = bs[n + 1];
                p1[(size_t)n * HW]       = fmaf((float)acc[f][g][0], s0, z0);
                p1[(size_t)(n + 1) * HW] = fmaf((float)acc[f][g][1], s1, z1);
                p2[(size_t)n * HW]       = fmaf((float)acc[f][g][2], s0, z0);
                p2[(size_t)(n + 1) * HW] = fmaf((float)acc[f][g][3], s1, z1);
            }
        }

        tile  = tile_next;
        aSrc0 = aSrc0_next;
    }
    CP_WAIT(0);                            // drain any in-flight groups before exit
}

// ---------------- launch ----------------
extern "C" void kernel_launch(void* const* d_in, const int* in_sizes, int n_in,
                              void* d_out, int out_size) {
    const float* x    = (const float*)d_in[0];
    const float* w    = (const float*)d_in[1];
    const float* bias = (const float*)d_in[2];
    const float* sw   = (const float*)d_in[3];
    const float* sx   = (const float*)d_in[4];
    float* out        = (float*)d_out;

    cudaFuncSetAttribute(conv_mma_kernel, cudaFuncAttributeMaxDynamicSharedMemorySize, SMEM_BYTES);

    prep_kernel<<<WQ_BLOCKS + B_ * H_, THREADS>>>(x, w, sw, sx);
    conv_mma_kernel<<<GRID, THREADS, SMEM_BYTES>>>(bias, sw, sx, out);
}